// round 16
// baseline (speedup 1.0000x reference)
#include <cuda_runtime.h>
#include <cuda_bf16.h>
#include <math_constants.h>
#include <cstdint>
#include <mma.h>

using namespace nvcuda;

#define N_NODES 50000
#define N_EDGES 600000
#define N_REL   64
#define DIM     128
#define DIM4    32

#define SCAN_B 1024
#define SCAN_G ((N_NODES + SCAN_B - 1) / SCAN_B)   // 49

typedef unsigned long long ull;

// ---------------- device scratch (no allocations allowed) ----------------
// Zero-initialized at load; each replay leaves deg/psync zeroed for the next
// one (scan zeroes deg after reading; scatter zeroes psync). cursor is
// (re)initialized to rowptr by scan every replay.
__device__ float g_prev[N_NODES * DIM];
__device__ float g_neigh[N_NODES * DIM];
__device__ int   g_deg[N_NODES];
__device__ int   g_cursor[N_NODES];
__device__ int   g_rowptr[N_NODES + 1];
__device__ ull   g_psync[SCAN_G];               // scan lookback: bit63 flag | sum
__device__ ull   g_edge[N_EDGES];               // packed (rel << 32) | nbr
// W split: [layer][k-chunk128] -> 64KB blob: 32KB hi (128x128 bf16 [k][n]) + 32KB lo
__device__ __align__(16) unsigned char g_Wsw[2][2][65536];

__device__ __forceinline__ float tanh_fast(float x) {
    float y; asm("tanh.approx.f32 %0, %1;" : "=f"(y) : "f"(x)); return y;
}

// ---------------- count (+ one-time W split) ----------------
__global__ void k_count(const int* __restrict__ dst,
                        const float* __restrict__ W)
{
    int e = blockIdx.x * blockDim.x + threadIdx.x;
    if (e < N_EDGES) atomicAdd(&g_deg[dst[e]], 1);

    if (e < 2 * 2 * 128 * 128) {
        int l  = e >> 15;
        int r  = e & 32767;
        int kc = r >> 14; r &= 16383;
        int k  = r >> 7;
        int n  = r & 127;
        float w = W[(l * 256 + kc * 128 + k) * 128 + n];
        __nv_bfloat16 hi = __float2bfloat16(w);
        __nv_bfloat16 lo = __float2bfloat16(w - __bfloat162float(hi));
        __nv_bfloat16* base = (__nv_bfloat16*)&g_Wsw[l][kc][0];
        base[k * 128 + n]         = hi;
        base[16384 + k * 128 + n] = lo;
    }
}

// single-launch scan: block-local scan + decoupled lookback over 49 partials.
__global__ void k_scan()
{
    __shared__ int warpsum[32];
    __shared__ int s_prefix;
    const int lane = threadIdx.x & 31;
    const int wid  = threadIdx.x >> 5;
    const int b    = blockIdx.x;
    const int i    = b * SCAN_B + threadIdx.x;

    int v = (i < N_NODES) ? g_deg[i] : 0;
    if (i < N_NODES) g_deg[i] = 0;

    int s = v;
    #pragma unroll
    for (int o = 1; o < 32; o <<= 1) {
        int u = __shfl_up_sync(0xffffffffu, s, o);
        if (lane >= o) s += u;
    }
    if (lane == 31) warpsum[wid] = s;
    __syncthreads();
    if (wid == 0) {
        int ws = warpsum[lane];
        #pragma unroll
        for (int o = 1; o < 32; o <<= 1) {
            int u = __shfl_up_sync(0xffffffffu, ws, o);
            if (lane >= o) ws += u;
        }
        warpsum[lane] = ws;
    }
    __syncthreads();
    const int incl = s + (wid ? warpsum[wid - 1] : 0);

    if (threadIdx.x == SCAN_B - 1)
        atomicExch(&g_psync[b], (1ull << 63) | (ull)(unsigned)incl);

    if (wid == 0) {
        int pre = 0;
        for (int pb = lane; pb < b; pb += 32) {
            ull w;
            do { w = atomicAdd(&g_psync[pb], 0ull); } while (!(w >> 63));
            pre += (int)(w & 0x7fffffffu);
        }
        #pragma unroll
        for (int o = 16; o; o >>= 1)
            pre += __shfl_xor_sync(0xffffffffu, pre, o);
        if (lane == 0) s_prefix = pre;
    }
    __syncthreads();

    if (i < N_NODES) {
        int ex = incl - v + s_prefix;
        g_rowptr[i] = ex;
        g_cursor[i] = ex;                 // scatter increments from here
    }
    if (b == SCAN_G - 1 && threadIdx.x == SCAN_B - 1)
        g_rowptr[N_NODES] = incl + s_prefix;
}

__global__ void k_scatter(const int* __restrict__ dst,
                          const int* __restrict__ nbr,
                          const int* __restrict__ rel)
{
    int e = blockIdx.x * blockDim.x + threadIdx.x;
    if (e < N_EDGES) {
        int pos = atomicAdd(&g_cursor[dst[e]], 1);
        g_edge[pos] = ((ull)(unsigned)rel[e] << 32) | (unsigned)nbr[e];
    }
    if (e < SCAN_G) g_psync[e] = 0ull;        // reset for next replay
}

// ---------------- attention: one warp per node (R14 measured-best form) ----
// No max-subtraction (|score| small by Cauchy-Schwarz -> exp safe in fp32).
// Predicate-free 4x main loop + scalar tail. Relation table (32KB) staged in
// shared memory per block: LDS (29cyc, conflict-free) replaces L1 LDG (39cyc)
// on the critical chain into tanh. Register- and instruction-count-neutral.
__global__ void __launch_bounds__(256)
k_attn(const float* __restrict__ in,
       const float* __restrict__ entity,
       const float* __restrict__ relation)
{
    __shared__ float4 srel[N_REL * DIM4];             // 32KB

    // cooperative preload BEFORE any early return
    {
        const float4* rel4 = (const float4*)relation;
        #pragma unroll
        for (int p = 0; p < 8; ++p)
            srel[p * 256 + threadIdx.x] = rel4[p * 256 + threadIdx.x];
    }
    __syncthreads();

    const int wid  = threadIdx.x >> 5;
    const int lane = threadIdx.x & 31;
    const int node = blockIdx.x * 8 + wid;
    if (node >= N_NODES) return;

    const int start = g_rowptr[node];
    const int end   = g_rowptr[node + 1];
    if (start == end) return;                         // epilogue handles deg==0

    const float4* ent4 = (const float4*)entity;
    const float4* in4  = (const float4*)in;
    float4*       ng4  = (float4*)g_neigh;

    float4 ed = ent4[node * DIM4 + lane];

    float  dsum = 0.f;
    float4 acc  = make_float4(0.f, 0.f, 0.f, 0.f);

    const int nfull = (end - start) & ~3;
    const int mid   = start + nfull;

    for (int base = start; base < mid; base += 4) {
        float4 x[4];
        float  s[4];
        #pragma unroll
        for (int i = 0; i < 4; ++i) {
            ull ev = g_edge[base + i];
            int nb = (int)(ev & 0xffffffffu);
            int rl = (int)(ev >> 32);
            x[i] = in4[nb * DIM4 + lane];
            float4 r = srel[rl * DIM4 + lane];
            float qx = tanh_fast(ed.x + r.x);
            float qy = tanh_fast(ed.y + r.y);
            float qz = tanh_fast(ed.z + r.z);
            float qw = tanh_fast(ed.w + r.w);
            s[i] = x[i].x * qx + x[i].y * qy + x[i].z * qz + x[i].w * qw;
        }
        #pragma unroll
        for (int off = 16; off; off >>= 1) {
            #pragma unroll
            for (int i = 0; i < 4; ++i)
                s[i] += __shfl_xor_sync(0xffffffffu, s[i], off);
        }
        #pragma unroll
        for (int i = 0; i < 4; ++i) {
            float w = __expf(s[i]);
            dsum += w;
            acc.x += w * x[i].x; acc.y += w * x[i].y;
            acc.z += w * x[i].z; acc.w += w * x[i].w;
        }
    }
    for (int e = mid; e < end; ++e) {                 // scalar tail (<=3 edges)
        ull ev = g_edge[e];
        int nb = (int)(ev & 0xffffffffu);
        int rl = (int)(ev >> 32);
        float4 x = in4[nb * DIM4 + lane];
        float4 r = srel[rl * DIM4 + lane];
        float qx = tanh_fast(ed.x + r.x);
        float qy = tanh_fast(ed.y + r.y);
        float qz = tanh_fast(ed.z + r.z);
        float qw = tanh_fast(ed.w + r.w);
        float s = x.x * qx + x.y * qy + x.z * qz + x.w * qw;
        #pragma unroll
        for (int off = 16; off; off >>= 1)
            s += __shfl_xor_sync(0xffffffffu, s, off);
        float w = __expf(s);
        dsum += w;
        acc.x += w * x.x; acc.y += w * x.y; acc.z += w * x.z; acc.w += w * x.w;
    }

    const float inv = 1.0f / dsum;
    ng4[node * DIM4 + lane] = make_float4(acc.x * inv, acc.y * inv,
                                          acc.z * inv, acc.w * inv);
}

// ---------------- WMMA bf16x3 GEMM + epilogue (R14 form — measured best) ----
// BM=128; K=256 in FOUR K64 chunks -> smem ~71KB -> 2 blocks/SM:
// one block's HMMA overlaps the other's stage/convert phase.
// D += Ahi*Bhi + Ahi*Blo + Alo*Bhi  (f32 accumulate)
#define AS_STRIDE 72                        // bf16 elems per A row (64 + pad 8)
#define BS_STRIDE 136                       // bf16 elems per B row (128 + pad 8)
#define CS_STRIDE 132                       // f32 elems per C row (128 + pad 4)
#define SM_BIAS   0
#define SM_A_HI   1024
#define SM_A_LO   (SM_A_HI + 128 * AS_STRIDE * 2)     // +18432
#define SM_B_HI   (SM_A_LO + 128 * AS_STRIDE * 2)
#define SM_B_LO   (SM_B_HI + 64 * BS_STRIDE * 2)      // +17408
#define SM_C      1024                      // reuses A+B region after MMA
#define SMEM_TOTAL (SM_B_LO + 64 * BS_STRIDE * 2)     // 72704

__global__ void __launch_bounds__(256, 2)
k_mma(const float* __restrict__ in,
      const float* __restrict__ neigh,
      const unsigned char* __restrict__ wsw,   // g_Wsw[layer]: 2 x 64KB blobs
      const float* __restrict__ bl,
      const float* __restrict__ entity,
      float*       __restrict__ out)
{
    extern __shared__ unsigned char smem[];
    const int t      = threadIdx.x;
    const int wid    = t >> 5;
    const int warp_m = wid >> 2;
    const int warp_n = wid & 3;
    const int m0     = blockIdx.x * 128;

    float* sbias = (float*)(smem + SM_BIAS);
    if (t < 128) sbias[t] = bl[t];

    __nv_bfloat16* Ah = (__nv_bfloat16*)(smem + SM_A_HI);
    __nv_bfloat16* Al = (__nv_bfloat16*)(smem + SM_A_LO);
    __nv_bfloat16* Bh = (__nv_bfloat16*)(smem + SM_B_HI);
    __nv_bfloat16* Bl = (__nv_bfloat16*)(smem + SM_B_LO);

    wmma::fragment<wmma::accumulator, 16, 16, 16, float> c[4][2];
    #pragma unroll
    for (int mt = 0; mt < 4; ++mt)
        #pragma unroll
        for (int nt = 0; nt < 2; ++nt)
            wmma::fill_fragment(c[mt][nt], 0.f);

    for (int ch = 0; ch < 4; ++ch) {
        const float* Asrc = (ch < 2) ? in : neigh;
        const int koff = (ch & 1) * 64;
        __syncthreads();

        // A chunk [128 x 64] fp32 -> bf16 hi/lo into padded smem
        #pragma unroll
        for (int p = 0; p < 8; ++p) {
            int f   = p * 256 + t;           // 2048 float4
            int row = f >> 4;
            int c4  = f & 15;
            int node = m0 + row;
            float4 v = make_float4(0.f, 0.f, 0.f, 0.f);
            if (node < N_NODES)
                v = *(const float4*)(Asrc + node * DIM + koff + c4 * 4);

            __nv_bfloat16 h0 = __float2bfloat16(v.x);
            __nv_bfloat16 h1 = __float2bfloat16(v.y);
            __nv_bfloat16 h2 = __float2bfloat16(v.z);
            __nv_bfloat16 h3 = __float2bfloat16(v.w);
            __nv_bfloat16 l0 = __float2bfloat16(v.x - __bfloat162float(h0));
            __nv_bfloat16 l1 = __float2bfloat16(v.y - __bfloat162float(h1));
            __nv_bfloat16 l2 = __float2bfloat16(v.z - __bfloat162float(h2));
            __nv_bfloat16 l3 = __float2bfloat16(v.w - __bfloat162float(h3));

            ull ph = (ull)__bfloat16_as_ushort(h0)
                   | ((ull)__bfloat16_as_ushort(h1) << 16)
                   | ((ull)__bfloat16_as_ushort(h2) << 32)
                   | ((ull)__bfloat16_as_ushort(h3) << 48);
            ull pl = (ull)__bfloat16_as_ushort(l0)
                   | ((ull)__bfloat16_as_ushort(l1) << 16)
                   | ((ull)__bfloat16_as_ushort(l2) << 32)
                   | ((ull)__bfloat16_as_ushort(l3) << 48);

            int eo = row * AS_STRIDE + c4 * 4;
            *(ull*)(Ah + eo) = ph;
            *(ull*)(Al + eo) = pl;
        }
        // B chunk: rows [koff, koff+64) of W blob (ch>>1) into padded smem
        {
            const uint32_t* sh = (const uint32_t*)(wsw + (ch >> 1) * 65536)
                               + koff * 64;
            const uint32_t* sl = (const uint32_t*)(wsw + (ch >> 1) * 65536 + 32768)
                               + koff * 64;
            #pragma unroll
            for (int p = 0; p < 16; ++p) {
                int idx = p * 256 + t;       // 4096 uint32
                int row = idx >> 6;
                int cp  = idx & 63;
                int eo  = row * BS_STRIDE + cp * 2;
                *(uint32_t*)(Bh + eo) = sh[idx];
                *(uint32_t*)(Bl + eo) = sl[idx];
            }
        }
        __syncthreads();

        #pragma unroll
        for (int ks = 0; ks < 4; ++ks) {
            wmma::fragment<wmma::matrix_b, 16, 16, 16, __nv_bfloat16,
                           wmma::row_major> bh[2], blo[2];
            #pragma unroll
            for (int nt = 0; nt < 2; ++nt) {
                int ncol = warp_n * 32 + nt * 16;
                wmma::load_matrix_sync(bh[nt],  Bh + ks * 16 * BS_STRIDE + ncol,
                                       BS_STRIDE);
                wmma::load_matrix_sync(blo[nt], Bl + ks * 16 * BS_STRIDE + ncol,
                                       BS_STRIDE);
            }
            #pragma unroll
            for (int mt = 0; mt < 4; ++mt) {
                int mrow = warp_m * 64 + mt * 16;
                wmma::fragment<wmma::matrix_a, 16, 16, 16, __nv_bfloat16,
                               wmma::row_major> ah, alo;
                wmma::load_matrix_sync(ah,  Ah + mrow * AS_STRIDE + ks * 16,
                                       AS_STRIDE);
                wmma::load_matrix_sync(alo, Al + mrow * AS_STRIDE + ks * 16,
                                       AS_STRIDE);
                #pragma unroll
                for (int nt = 0; nt < 2; ++nt) {
                    wmma::mma_sync(c[mt][nt], ah,  bh[nt],  c[mt][nt]);
                    wmma::mma_sync(c[mt][nt], ah,  blo[nt], c[mt][nt]);
                    wmma::mma_sync(c[mt][nt], alo, bh[nt],  c[mt][nt]);
                }
            }
        }
    }
    __syncthreads();

    float* Cs = (float*)(smem + SM_C);
    #pragma unroll
    for (int mt = 0; mt < 4; ++mt)
        #pragma unroll
        for (int nt = 0; nt < 2; ++nt)
            wmma::store_matrix_sync(Cs + (warp_m * 64 + mt * 16) * CS_STRIDE
                                       + warp_n * 32 + nt * 16,
                                    c[mt][nt], CS_STRIDE, wmma::mem_row_major);
    __syncthreads();

    // epilogue: 2 threads per row (64 cols each): bias + leaky + L2 norm
    {
        const int r    = t >> 1;
        const int half = t & 1;
        const int node = m0 + r;
        const float* crow = Cs + r * CS_STRIDE + half * 64;
        const float* brow = sbias + half * 64;

        float sq = 0.f;
        #pragma unroll
        for (int j = 0; j < 64; ++j) {
            float v = crow[j] + brow[j];
            v = (v > 0.f) ? v : 0.01f * v;
            sq += v * v;
        }
        sq += __shfl_xor_sync(0xffffffffu, sq, 1);
        float rn = rsqrtf(sq);

        if (node < N_NODES) {
            int deg = g_rowptr[node + 1] - g_rowptr[node];
            float4*       out4 = (float4*)out;
            const float4* ent4 = (const float4*)entity;
            #pragma unroll
            for (int j4 = 0; j4 < 16; ++j4) {
                float4 o;
                if (deg == 0) {
                    o = ent4[node * DIM4 + half * 16 + j4];
                } else {
                    float v0 = crow[j4 * 4 + 0] + brow[j4 * 4 + 0];
                    float v1 = crow[j4 * 4 + 1] + brow[j4 * 4 + 1];
                    float v2 = crow[j4 * 4 + 2] + brow[j4 * 4 + 2];
                    float v3 = crow[j4 * 4 + 3] + brow[j4 * 4 + 3];
                    o.x = ((v0 > 0.f) ? v0 : 0.01f * v0) * rn;
                    o.y = ((v1 > 0.f) ? v1 : 0.01f * v1) * rn;
                    o.z = ((v2 > 0.f) ? v2 : 0.01f * v2) * rn;
                    o.w = ((v3 > 0.f) ? v3 : 0.01f * v3) * rn;
                }
                out4[node * DIM4 + half * 16 + j4] = o;
            }
        }
    }
}

// ---------------- launch ----------------
extern "C" void kernel_launch(void* const* d_in, const int* in_sizes, int n_in,
                              void* d_out, int out_size)
{
    const float* entity   = (const float*)d_in[0];
    const float* relation = (const float*)d_in[1];
    const float* W        = (const float*)d_in[2];
    const float* b        = (const float*)d_in[3];
    const int*   edst     = (const int*)d_in[4];
    const int*   enbr     = (const int*)d_in[5];
    const int*   erel     = (const int*)d_in[6];
    float*       out      = (float*)d_out;

    float* prev  = nullptr;
    float* neigh = nullptr;
    unsigned char* wsw = nullptr;
    cudaGetSymbolAddress((void**)&prev,  g_prev);
    cudaGetSymbolAddress((void**)&neigh, g_neigh);
    cudaGetSymbolAddress((void**)&wsw,   g_Wsw);

    cudaFuncSetAttribute(k_mma, cudaFuncAttributeMaxDynamicSharedMemorySize,
                         SMEM_TOTAL);

    const int TB = 256;
    const int agrid = (N_NODES + 7) / 8;
    const int ggrid = (N_NODES + 127) / 128;

    // deg/psync are zero on entry (zero-init at load; scan/scatter re-zero
    // them each replay). cursor is set by scan.
    k_count  <<<(N_EDGES + TB - 1) / TB, TB>>>(edst, W);            // #1
    k_scan   <<<SCAN_G, SCAN_B>>>();                                // #2
    k_scatter<<<(N_EDGES + TB - 1) / TB, TB>>>(edst, enbr, erel);   // #3
    // layer 0
    k_attn<<<agrid, TB>>>(entity, entity, relation);                // #4 (profiled)
    k_mma <<<ggrid, TB, SMEM_TOTAL>>>(entity, neigh, wsw + 0 * 2 * 65536,
                                      b + 0 * DIM, entity, prev);   // #5
    // layer 1
    k_attn<<<agrid, TB>>>(prev, entity, relation);                  // #6
    k_mma <<<ggrid, TB, SMEM_TOTAL>>>(prev, neigh, wsw + 1 * 2 * 65536,
                                      b + 1 * DIM, entity, out);    // #7
}

// round 17
// speedup vs baseline: 1.1292x; 1.1292x over previous
#include <cuda_runtime.h>
#include <cuda_bf16.h>
#include <math_constants.h>
#include <cstdint>
#include <mma.h>

using namespace nvcuda;

#define N_NODES 50000
#define N_EDGES 600000
#define N_REL   64
#define DIM     128
#define DIM4    32

#define SCAN_B 1024
#define SCAN_G ((N_NODES + SCAN_B - 1) / SCAN_B)   // 49

typedef unsigned long long ull;

// ---------------- device scratch (no allocations allowed) ----------------
// Zero-initialized at load; each replay leaves deg/psync zeroed for the next
// one (scan zeroes deg after reading; scatter zeroes psync). cursor is
// (re)initialized to rowptr by scan every replay.
__device__ float g_prev[N_NODES * DIM];
__device__ float g_neigh[N_NODES * DIM];
__device__ int   g_deg[N_NODES];
__device__ int   g_cursor[N_NODES];
__device__ int   g_rowptr[N_NODES + 1];
__device__ ull   g_psync[SCAN_G];               // scan lookback: bit63 flag | sum
__device__ ull   g_edge[N_EDGES];               // packed (rel << 32) | nbr
// W split: [layer][k-chunk128] -> 64KB blob: 32KB hi (128x128 bf16 [k][n]) + 32KB lo
__device__ __align__(16) unsigned char g_Wsw[2][2][65536];

__device__ __forceinline__ float tanh_fast(float x) {
    float y; asm("tanh.approx.f32 %0, %1;" : "=f"(y) : "f"(x)); return y;
}

// ---------------- count (+ one-time W split) ----------------
__global__ void k_count(const int* __restrict__ dst,
                        const float* __restrict__ W)
{
    int e = blockIdx.x * blockDim.x + threadIdx.x;
    if (e < N_EDGES) atomicAdd(&g_deg[dst[e]], 1);

    if (e < 2 * 2 * 128 * 128) {
        int l  = e >> 15;
        int r  = e & 32767;
        int kc = r >> 14; r &= 16383;
        int k  = r >> 7;
        int n  = r & 127;
        float w = W[(l * 256 + kc * 128 + k) * 128 + n];
        __nv_bfloat16 hi = __float2bfloat16(w);
        __nv_bfloat16 lo = __float2bfloat16(w - __bfloat162float(hi));
        __nv_bfloat16* base = (__nv_bfloat16*)&g_Wsw[l][kc][0];
        base[k * 128 + n]         = hi;
        base[16384 + k * 128 + n] = lo;
    }
}

// single-launch scan: block-local scan + decoupled lookback over 49 partials.
__global__ void k_scan()
{
    __shared__ int warpsum[32];
    __shared__ int s_prefix;
    const int lane = threadIdx.x & 31;
    const int wid  = threadIdx.x >> 5;
    const int b    = blockIdx.x;
    const int i    = b * SCAN_B + threadIdx.x;

    int v = (i < N_NODES) ? g_deg[i] : 0;
    if (i < N_NODES) g_deg[i] = 0;

    int s = v;
    #pragma unroll
    for (int o = 1; o < 32; o <<= 1) {
        int u = __shfl_up_sync(0xffffffffu, s, o);
        if (lane >= o) s += u;
    }
    if (lane == 31) warpsum[wid] = s;
    __syncthreads();
    if (wid == 0) {
        int ws = warpsum[lane];
        #pragma unroll
        for (int o = 1; o < 32; o <<= 1) {
            int u = __shfl_up_sync(0xffffffffu, ws, o);
            if (lane >= o) ws += u;
        }
        warpsum[lane] = ws;
    }
    __syncthreads();
    const int incl = s + (wid ? warpsum[wid - 1] : 0);

    if (threadIdx.x == SCAN_B - 1)
        atomicExch(&g_psync[b], (1ull << 63) | (ull)(unsigned)incl);

    if (wid == 0) {
        int pre = 0;
        for (int pb = lane; pb < b; pb += 32) {
            ull w;
            do { w = atomicAdd(&g_psync[pb], 0ull); } while (!(w >> 63));
            pre += (int)(w & 0x7fffffffu);
        }
        #pragma unroll
        for (int o = 16; o; o >>= 1)
            pre += __shfl_xor_sync(0xffffffffu, pre, o);
        if (lane == 0) s_prefix = pre;
    }
    __syncthreads();

    if (i < N_NODES) {
        int ex = incl - v + s_prefix;
        g_rowptr[i] = ex;
        g_cursor[i] = ex;                 // scatter increments from here
    }
    if (b == SCAN_G - 1 && threadIdx.x == SCAN_B - 1)
        g_rowptr[N_NODES] = incl + s_prefix;
}

__global__ void k_scatter(const int* __restrict__ dst,
                          const int* __restrict__ nbr,
                          const int* __restrict__ rel)
{
    int e = blockIdx.x * blockDim.x + threadIdx.x;
    if (e < N_EDGES) {
        int pos = atomicAdd(&g_cursor[dst[e]], 1);
        g_edge[pos] = ((ull)(unsigned)rel[e] << 32) | (unsigned)nbr[e];
    }
    if (e < SCAN_G) g_psync[e] = 0ull;        // reset for next replay
}

// ---------------- attention: one warp per node (R14 measured-best, FROZEN) --
// No max-subtraction (|score| small by Cauchy-Schwarz -> exp safe in fp32).
// Predicate-free 4x main loop + scalar tail. Do not perturb: reg cap, smem
// staging, half-warp edges, and bf16 relation all measured slower.
__global__ void __launch_bounds__(256)
k_attn(const float* __restrict__ in,
       const float* __restrict__ entity,
       const float* __restrict__ relation)
{
    const int wid  = threadIdx.x >> 5;
    const int lane = threadIdx.x & 31;
    const int node = blockIdx.x * 8 + wid;
    if (node >= N_NODES) return;

    const int start = g_rowptr[node];
    const int end   = g_rowptr[node + 1];
    if (start == end) return;                         // epilogue handles deg==0

    const float4* ent4 = (const float4*)entity;
    const float4* in4  = (const float4*)in;
    const float4* rel4 = (const float4*)relation;
    float4*       ng4  = (float4*)g_neigh;

    float4 ed = ent4[node * DIM4 + lane];

    float  dsum = 0.f;
    float4 acc  = make_float4(0.f, 0.f, 0.f, 0.f);

    const int nfull = (end - start) & ~3;
    const int mid   = start + nfull;

    for (int base = start; base < mid; base += 4) {
        float4 x[4];
        float  s[4];
        #pragma unroll
        for (int i = 0; i < 4; ++i) {
            ull ev = g_edge[base + i];
            int nb = (int)(ev & 0xffffffffu);
            int rl = (int)(ev >> 32);
            x[i] = in4[nb * DIM4 + lane];
            float4 r = rel4[rl * DIM4 + lane];
            float qx = tanh_fast(ed.x + r.x);
            float qy = tanh_fast(ed.y + r.y);
            float qz = tanh_fast(ed.z + r.z);
            float qw = tanh_fast(ed.w + r.w);
            s[i] = x[i].x * qx + x[i].y * qy + x[i].z * qz + x[i].w * qw;
        }
        #pragma unroll
        for (int off = 16; off; off >>= 1) {
            #pragma unroll
            for (int i = 0; i < 4; ++i)
                s[i] += __shfl_xor_sync(0xffffffffu, s[i], off);
        }
        #pragma unroll
        for (int i = 0; i < 4; ++i) {
            float w = __expf(s[i]);
            dsum += w;
            acc.x += w * x[i].x; acc.y += w * x[i].y;
            acc.z += w * x[i].z; acc.w += w * x[i].w;
        }
    }
    for (int e = mid; e < end; ++e) {                 // scalar tail (<=3 edges)
        ull ev = g_edge[e];
        int nb = (int)(ev & 0xffffffffu);
        int rl = (int)(ev >> 32);
        float4 x = in4[nb * DIM4 + lane];
        float4 r = rel4[rl * DIM4 + lane];
        float qx = tanh_fast(ed.x + r.x);
        float qy = tanh_fast(ed.y + r.y);
        float qz = tanh_fast(ed.z + r.z);
        float qw = tanh_fast(ed.w + r.w);
        float s = x.x * qx + x.y * qy + x.z * qz + x.w * qw;
        #pragma unroll
        for (int off = 16; off; off >>= 1)
            s += __shfl_xor_sync(0xffffffffu, s, off);
        float w = __expf(s);
        dsum += w;
        acc.x += w * x.x; acc.y += w * x.y; acc.z += w * x.z; acc.w += w * x.w;
    }

    const float inv = 1.0f / dsum;
    ng4[node * DIM4 + lane] = make_float4(acc.x * inv, acc.y * inv,
                                          acc.z * inv, acc.w * inv);
}

// ---------------- WMMA bf16x3 GEMM + epilogue (R14 + uint4 B copy) ----------
// BM=128; K=256 in FOUR K64 chunks -> smem ~71KB -> 2 blocks/SM:
// one block's HMMA overlaps the other's stage/convert phase.
// D += Ahi*Bhi + Ahi*Blo + Alo*Bhi  (f32 accumulate)
#define AS_STRIDE 72                        // bf16 elems per A row (64 + pad 8)
#define BS_STRIDE 136                       // bf16 elems per B row (128 + pad 8)
#define CS_STRIDE 132                       // f32 elems per C row (128 + pad 4)
#define SM_BIAS   0
#define SM_A_HI   1024
#define SM_A_LO   (SM_A_HI + 128 * AS_STRIDE * 2)     // +18432
#define SM_B_HI   (SM_A_LO + 128 * AS_STRIDE * 2)
#define SM_B_LO   (SM_B_HI + 64 * BS_STRIDE * 2)      // +17408
#define SM_C      1024                      // reuses A+B region after MMA
#define SMEM_TOTAL (SM_B_LO + 64 * BS_STRIDE * 2)     // 72704

__global__ void __launch_bounds__(256, 2)
k_mma(const float* __restrict__ in,
      const float* __restrict__ neigh,
      const unsigned char* __restrict__ wsw,   // g_Wsw[layer]: 2 x 64KB blobs
      const float* __restrict__ bl,
      const float* __restrict__ entity,
      float*       __restrict__ out)
{
    extern __shared__ unsigned char smem[];
    const int t      = threadIdx.x;
    const int wid    = t >> 5;
    const int warp_m = wid >> 2;
    const int warp_n = wid & 3;
    const int m0     = blockIdx.x * 128;

    float* sbias = (float*)(smem + SM_BIAS);
    if (t < 128) sbias[t] = bl[t];

    __nv_bfloat16* Ah = (__nv_bfloat16*)(smem + SM_A_HI);
    __nv_bfloat16* Al = (__nv_bfloat16*)(smem + SM_A_LO);
    __nv_bfloat16* Bh = (__nv_bfloat16*)(smem + SM_B_HI);
    __nv_bfloat16* Bl = (__nv_bfloat16*)(smem + SM_B_LO);

    wmma::fragment<wmma::accumulator, 16, 16, 16, float> c[4][2];
    #pragma unroll
    for (int mt = 0; mt < 4; ++mt)
        #pragma unroll
        for (int nt = 0; nt < 2; ++nt)
            wmma::fill_fragment(c[mt][nt], 0.f);

    for (int ch = 0; ch < 4; ++ch) {
        const float* Asrc = (ch < 2) ? in : neigh;
        const int koff = (ch & 1) * 64;
        __syncthreads();

        // A chunk [128 x 64] fp32 -> bf16 hi/lo into padded smem
        #pragma unroll
        for (int p = 0; p < 8; ++p) {
            int f   = p * 256 + t;           // 2048 float4
            int row = f >> 4;
            int c4  = f & 15;
            int node = m0 + row;
            float4 v = make_float4(0.f, 0.f, 0.f, 0.f);
            if (node < N_NODES)
                v = *(const float4*)(Asrc + node * DIM + koff + c4 * 4);

            __nv_bfloat16 h0 = __float2bfloat16(v.x);
            __nv_bfloat16 h1 = __float2bfloat16(v.y);
            __nv_bfloat16 h2 = __float2bfloat16(v.z);
            __nv_bfloat16 h3 = __float2bfloat16(v.w);
            __nv_bfloat16 l0 = __float2bfloat16(v.x - __bfloat162float(h0));
            __nv_bfloat16 l1 = __float2bfloat16(v.y - __bfloat162float(h1));
            __nv_bfloat16 l2 = __float2bfloat16(v.z - __bfloat162float(h2));
            __nv_bfloat16 l3 = __float2bfloat16(v.w - __bfloat162float(h3));

            ull ph = (ull)__bfloat16_as_ushort(h0)
                   | ((ull)__bfloat16_as_ushort(h1) << 16)
                   | ((ull)__bfloat16_as_ushort(h2) << 32)
                   | ((ull)__bfloat16_as_ushort(h3) << 48);
            ull pl = (ull)__bfloat16_as_ushort(l0)
                   | ((ull)__bfloat16_as_ushort(l1) << 16)
                   | ((ull)__bfloat16_as_ushort(l2) << 32)
                   | ((ull)__bfloat16_as_ushort(l3) << 48);

            int eo = row * AS_STRIDE + c4 * 4;
            *(ull*)(Ah + eo) = ph;
            *(ull*)(Al + eo) = pl;
        }
        // B chunk: rows [koff, koff+64) of W blob (ch>>1) into padded smem.
        // uint4 copies: src rows 256B, dst rows 272B (17x16B) — both 16B-aligned.
        {
            const uint4* sh = (const uint4*)(wsw + (ch >> 1) * 65536 + koff * 256);
            const uint4* sl = (const uint4*)(wsw + (ch >> 1) * 65536 + 32768
                                             + koff * 256);
            #pragma unroll
            for (int p = 0; p < 4; ++p) {
                int idx = p * 256 + t;       // 1024 uint4 per tile
                int row = idx >> 4;
                int c16 = idx & 15;
                int eo  = row * BS_STRIDE + c16 * 8;   // bf16 elements
                *(uint4*)(Bh + eo) = sh[idx];
                *(uint4*)(Bl + eo) = sl[idx];
            }
        }
        __syncthreads();

        #pragma unroll
        for (int ks = 0; ks < 4; ++ks) {
            wmma::fragment<wmma::matrix_b, 16, 16, 16, __nv_bfloat16,
                           wmma::row_major> bh[2], blo[2];
            #pragma unroll
            for (int nt = 0; nt < 2; ++nt) {
                int ncol = warp_n * 32 + nt * 16;
                wmma::load_matrix_sync(bh[nt],  Bh + ks * 16 * BS_STRIDE + ncol,
                                       BS_STRIDE);
                wmma::load_matrix_sync(blo[nt], Bl + ks * 16 * BS_STRIDE + ncol,
                                       BS_STRIDE);
            }
            #pragma unroll
            for (int mt = 0; mt < 4; ++mt) {
                int mrow = warp_m * 64 + mt * 16;
                wmma::fragment<wmma::matrix_a, 16, 16, 16, __nv_bfloat16,
                               wmma::row_major> ah, alo;
                wmma::load_matrix_sync(ah,  Ah + mrow * AS_STRIDE + ks * 16,
                                       AS_STRIDE);
                wmma::load_matrix_sync(alo, Al + mrow * AS_STRIDE + ks * 16,
                                       AS_STRIDE);
                #pragma unroll
                for (int nt = 0; nt < 2; ++nt) {
                    wmma::mma_sync(c[mt][nt], ah,  bh[nt],  c[mt][nt]);
                    wmma::mma_sync(c[mt][nt], ah,  blo[nt], c[mt][nt]);
                    wmma::mma_sync(c[mt][nt], alo, bh[nt],  c[mt][nt]);
                }
            }
        }
    }
    __syncthreads();

    float* Cs = (float*)(smem + SM_C);
    #pragma unroll
    for (int mt = 0; mt < 4; ++mt)
        #pragma unroll
        for (int nt = 0; nt < 2; ++nt)
            wmma::store_matrix_sync(Cs + (warp_m * 64 + mt * 16) * CS_STRIDE
                                       + warp_n * 32 + nt * 16,
                                    c[mt][nt], CS_STRIDE, wmma::mem_row_major);
    __syncthreads();

    // epilogue: 2 threads per row (64 cols each): bias + leaky + L2 norm
    {
        const int r    = t >> 1;
        const int half = t & 1;
        const int node = m0 + r;
        const float* crow = Cs + r * CS_STRIDE + half * 64;
        const float* brow = sbias + half * 64;

        float sq = 0.f;
        #pragma unroll
        for (int j = 0; j < 64; ++j) {
            float v = crow[j] + brow[j];
            v = (v > 0.f) ? v : 0.01f * v;
            sq += v * v;
        }
        sq += __shfl_xor_sync(0xffffffffu, sq, 1);
        float rn = rsqrtf(sq);

        if (node < N_NODES) {
            int deg = g_rowptr[node + 1] - g_rowptr[node];
            float4*       out4 = (float4*)out;
            const float4* ent4 = (const float4*)entity;
            #pragma unroll
            for (int j4 = 0; j4 < 16; ++j4) {
                float4 o;
                if (deg == 0) {
                    o = ent4[node * DIM4 + half * 16 + j4];
                } else {
                    float v0 = crow[j4 * 4 + 0] + brow[j4 * 4 + 0];
                    float v1 = crow[j4 * 4 + 1] + brow[j4 * 4 + 1];
                    float v2 = crow[j4 * 4 + 2] + brow[j4 * 4 + 2];
                    float v3 = crow[j4 * 4 + 3] + brow[j4 * 4 + 3];
                    o.x = ((v0 > 0.f) ? v0 : 0.01f * v0) * rn;
                    o.y = ((v1 > 0.f) ? v1 : 0.01f * v1) * rn;
                    o.z = ((v2 > 0.f) ? v2 : 0.01f * v2) * rn;
                    o.w = ((v3 > 0.f) ? v3 : 0.01f * v3) * rn;
                }
                out4[node * DIM4 + half * 16 + j4] = o;
            }
        }
    }
}

// ---------------- launch ----------------
extern "C" void kernel_launch(void* const* d_in, const int* in_sizes, int n_in,
                              void* d_out, int out_size)
{
    const float* entity   = (const float*)d_in[0];
    const float* relation = (const float*)d_in[1];
    const float* W        = (const float*)d_in[2];
    const float* b        = (const float*)d_in[3];
    const int*   edst     = (const int*)d_in[4];
    const int*   enbr     = (const int*)d_in[5];
    const int*   erel     = (const int*)d_in[6];
    float*       out      = (float*)d_out;

    float* prev  = nullptr;
    float* neigh = nullptr;
    unsigned char* wsw = nullptr;
    cudaGetSymbolAddress((void**)&prev,  g_prev);
    cudaGetSymbolAddress((void**)&neigh, g_neigh);
    cudaGetSymbolAddress((void**)&wsw,   g_Wsw);

    cudaFuncSetAttribute(k_mma, cudaFuncAttributeMaxDynamicSharedMemorySize,
                         SMEM_TOTAL);

    const int TB = 256;
    const int agrid = (N_NODES + 7) / 8;
    const int ggrid = (N_NODES + 127) / 128;

    // deg/psync are zero on entry (zero-init at load; scan/scatter re-zero
    // them each replay). cursor is set by scan.
    k_count  <<<(N_EDGES + TB - 1) / TB, TB>>>(edst, W);            // #1
    k_scan   <<<SCAN_G, SCAN_B>>>();                                // #2
    k_scatter<<<(N_EDGES + TB - 1) / TB, TB>>>(edst, enbr, erel);   // #3
    // layer 0
    k_attn<<<agrid, TB>>>(entity, entity, relation);                // #4 (profiled)
    k_mma <<<ggrid, TB, SMEM_TOTAL>>>(entity, neigh, wsw + 0 * 2 * 65536,
                                      b + 0 * DIM, entity, prev);   // #5
    // layer 1
    k_attn<<<agrid, TB>>>(prev, entity, relation);                  // #6
    k_mma <<<ggrid, TB, SMEM_TOTAL>>>(prev, neigh, wsw + 1 * 2 * 65536,
                                      b + 1 * DIM, entity, out);    // #7
}